// round 13
// baseline (speedup 1.0000x reference)
#include <cuda_runtime.h>

#define NB 64
#define LC 4096
#define HD 768
#define PD 128
#define BUDGETF 200.0f

// Scratch (allocation-free rule: __device__ globals)
__device__ float d_q[NB * PD];      // q_b = qr_b @ Wq + bq
__device__ float d_U[NB * HD];      // u_b = Wc @ q_b
__device__ float d_qbias[NB];       // q_b . bc
__device__ int   d_len[NB];         // valid context length per batch
__device__ float d_s[NB * LC];      // match scores (only [0,len) valid)

// ---------------------------------------------------------------------------
// Kernel 1a: q[b,p] = qr[b,:] . Wq[:,p] + bq[p] ; qbias[b] = q_b . bc ;
//            len[b] = sum(mask[b,:])      (measured-fast round-4 form)
// ---------------------------------------------------------------------------
__global__ void __launch_bounds__(512) qproj_kernel(const float* __restrict__ qr,
                                                    const float* __restrict__ Wq,
                                                    const float* __restrict__ bq,
                                                    const float* __restrict__ bc,
                                                    const int* __restrict__ mask) {
    int b = blockIdx.x;
    __shared__ float sh_qr[HD];
    __shared__ float sh_part[512];
    __shared__ int sh_cnt[16];
    int tid = threadIdx.x;

    for (int i = tid; i < HD; i += 512) sh_qr[i] = qr[b * HD + i];

    int cnt = 0;
    for (int i = tid; i < LC; i += 512) cnt += mask[b * LC + i];
    #pragma unroll
    for (int off = 16; off; off >>= 1) cnt += __shfl_xor_sync(0xffffffffu, cnt, off);
    if ((tid & 31) == 0) sh_cnt[tid >> 5] = cnt;
    __syncthreads();
    if (tid == 0) {
        int t = 0;
        #pragma unroll
        for (int w = 0; w < 16; w++) t += sh_cnt[w];
        d_len[b] = t;
    }

    int p = tid & 127;
    int slice = tid >> 7;            // 0..3
    int h0 = slice * (HD / 4);       // 192 rows per slice
    float a0 = 0.f, a1 = 0.f, a2 = 0.f, a3 = 0.f;
    #pragma unroll 4
    for (int h = h0; h < h0 + HD / 4; h += 4) {
        a0 = fmaf(sh_qr[h + 0], Wq[(h + 0) * PD + p], a0);
        a1 = fmaf(sh_qr[h + 1], Wq[(h + 1) * PD + p], a1);
        a2 = fmaf(sh_qr[h + 2], Wq[(h + 2) * PD + p], a2);
        a3 = fmaf(sh_qr[h + 3], Wq[(h + 3) * PD + p], a3);
    }
    sh_part[tid] = (a0 + a1) + (a2 + a3);
    __syncthreads();

    if (tid < PD) {
        float q = sh_part[tid] + sh_part[PD + tid] + sh_part[2 * PD + tid]
                + sh_part[3 * PD + tid] + bq[tid];
        d_q[b * PD + tid] = q;
        sh_part[tid] = q;
    }
    __syncthreads();

    if (tid < 32) {
        float v = 0.f;
        #pragma unroll
        for (int k = 0; k < 4; k++)
            v = fmaf(sh_part[tid + 32 * k], bc[tid + 32 * k], v);
        #pragma unroll
        for (int off = 16; off; off >>= 1)
            v += __shfl_xor_sync(0xffffffffu, v, off);
        if (tid == 0) d_qbias[b] = v;
    }
}

// ---------------------------------------------------------------------------
// Kernel 1b: u[b,h] = Wc[h,:] . q_b  (warp per h, lanes over p; grid 64x4)
// ---------------------------------------------------------------------------
__global__ void __launch_bounds__(256) uproj_kernel(const float* __restrict__ Wc) {
    int b = blockIdx.x;
    int chunk = blockIdx.y;
    __shared__ float sh_q[PD];
    int tid = threadIdx.x;
    if (tid < PD) sh_q[tid] = d_q[b * PD + tid];
    __syncthreads();

    int warp = tid >> 5, lane = tid & 31;
    for (int hh = warp; hh < HD / 4; hh += 8) {
        int h = chunk * (HD / 4) + hh;
        const float* wr = Wc + (size_t)h * PD;
        float acc = wr[lane] * sh_q[lane];
        acc = fmaf(wr[lane + 32], sh_q[lane + 32], acc);
        acc = fmaf(wr[lane + 64], sh_q[lane + 64], acc);
        acc = fmaf(wr[lane + 96], sh_q[lane + 96], acc);
        #pragma unroll
        for (int off = 16; off; off >>= 1)
            acc += __shfl_xor_sync(0xffffffffu, acc, off);
        if (lane == 0) d_U[b * HD + h] = acc;
    }
}

// ---------------------------------------------------------------------------
// Kernel 2: s[b,j] = ctx[b,j,:].u_b + qbias for j < len[b].
// Warp handles 2 adjacent rows per iteration: 12 LDGs in flight, two
// dual-issuing FMA chains, interleaved shuffle reduces.
// ---------------------------------------------------------------------------
#define SCORE_BLOCKS 1184
#define NWARPS (SCORE_BLOCKS * 8)

__global__ void __launch_bounds__(256) score_kernel(const float* __restrict__ ctx) {
    __shared__ int sh_len[NB];
    __shared__ float sh_qb[NB];
    int tid = threadIdx.x;
    if (tid < NB) { sh_len[tid] = d_len[tid]; sh_qb[tid] = d_qbias[tid]; }
    __syncthreads();

    int warp = tid >> 5, lane = tid & 31;
    int gw = blockIdx.x * 8 + warp;

    for (int pr = gw; pr < NB * LC / 2; pr += NWARPS) {
        int r0 = pr * 2;
        int b = r0 >> 12;                // LC = 4096
        int j = r0 & (LC - 1);
        int len = sh_len[b];
        if (j >= len) continue;          // uniform within warp
        bool do1 = (j + 1 < len);        // uniform within warp

        const float4* row0 = (const float4*)(ctx + (size_t)r0 * HD);
        const float4* row1 = row0 + HD / 4;
        const float4* u4   = (const float4*)(d_U + b * HD);
        float bias = sh_qb[b];

        if (do1) {
            float acc0 = 0.f, acc1 = 0.f;
            #pragma unroll
            for (int i = 0; i < 6; i++) {    // 192 float4 / 32 lanes, x2 rows
                float4 a = __ldcs(row0 + lane + 32 * i);
                float4 c = __ldcs(row1 + lane + 32 * i);
                float4 w = __ldg(u4 + lane + 32 * i);
                acc0 = fmaf(a.x, w.x, acc0); acc1 = fmaf(c.x, w.x, acc1);
                acc0 = fmaf(a.y, w.y, acc0); acc1 = fmaf(c.y, w.y, acc1);
                acc0 = fmaf(a.z, w.z, acc0); acc1 = fmaf(c.z, w.z, acc1);
                acc0 = fmaf(a.w, w.w, acc0); acc1 = fmaf(c.w, w.w, acc1);
            }
            #pragma unroll
            for (int off = 16; off; off >>= 1) {
                acc0 += __shfl_xor_sync(0xffffffffu, acc0, off);
                acc1 += __shfl_xor_sync(0xffffffffu, acc1, off);
            }
            if (lane == 0) {
                d_s[r0]     = acc0 + bias;
                d_s[r0 + 1] = acc1 + bias;
            }
        } else {
            float acc = 0.f;
            #pragma unroll
            for (int i = 0; i < 6; i++) {
                float4 a = __ldcs(row0 + lane + 32 * i);
                float4 w = __ldg(u4 + lane + 32 * i);
                acc = fmaf(a.x, w.x, acc);
                acc = fmaf(a.y, w.y, acc);
                acc = fmaf(a.z, w.z, acc);
                acc = fmaf(a.w, w.w, acc);
            }
            #pragma unroll
            for (int off = 16; off; off >>= 1)
                acc += __shfl_xor_sync(0xffffffffu, acc, off);
            if (lane == 0) d_s[r0] = acc + bias;
        }
    }
}

// ---------------------------------------------------------------------------
// Kernel 3: tau solve — 6 rounds 8-ary + secant, 2 barriers/round (R12 form,
// measured fast) + fused scatter tail.
// ---------------------------------------------------------------------------
__device__ __forceinline__ float clip01(float v) {
    return fminf(fmaxf(v, 0.f), 1.f);
}

__global__ void __launch_bounds__(512) tau_kernel(const int* __restrict__ qe_arr,
                                                  float* __restrict__ out) {
    int b = blockIdx.x;
    const int NT = 512;
    __shared__ float redf[2][16 * 7];
    __shared__ float sh_tot[2][8];
    int tid = threadIdx.x, warp = tid >> 5, lane = tid & 31;
    int len = d_len[b];
    const float* sp = d_s + b * LC;

    float v[8];
    #pragma unroll
    for (int k = 0; k < 8; k++) {
        int i = tid + k * NT;
        v[k] = (i < len) ? sp[i] : -100000.0f;
    }

    float mx = -100000.0f, sum0 = 0.f;
    #pragma unroll
    for (int k = 0; k < 8; k++) {
        mx = fmaxf(mx, v[k]);
        sum0 += clip01(v[k]);
    }
    {
        #pragma unroll
        for (int off = 16; off; off >>= 1) {
            mx   = fmaxf(mx, __shfl_xor_sync(0xffffffffu, mx, off));
            sum0 += __shfl_xor_sync(0xffffffffu, sum0, off);
        }
        if (lane == 0) { redf[0][warp * 2] = mx; redf[0][warp * 2 + 1] = sum0; }
        __syncthreads();
        if (tid == 0) {
            float a = redf[0][0], s = redf[0][1];
            #pragma unroll
            for (int w = 1; w < 16; w++) {
                a = fmaxf(a, redf[0][w * 2]);
                s += redf[0][w * 2 + 1];
            }
            sh_tot[1][0] = a; sh_tot[1][1] = s;
        }
        __syncthreads();
        mx = sh_tot[1][0]; sum0 = sh_tot[1][1];
    }

    float tau = 0.f;
    if (sum0 > BUDGETF) {
        float lo = 0.f, hi = mx;
        float slo = sum0, shi = 0.f;
        for (int it = 0; it < 6; it++) {
            int par = it & 1;
            float step = (hi - lo) * 0.125f;
            float part[7];
            #pragma unroll
            for (int c = 0; c < 7; c++) part[c] = 0.f;
            #pragma unroll
            for (int k = 0; k < 8; k++) {
                float x = v[k] - lo;
                #pragma unroll
                for (int c = 0; c < 7; c++)
                    part[c] += clip01(x - (c + 1) * step);
            }
            #pragma unroll
            for (int c = 0; c < 7; c++) {
                #pragma unroll
                for (int off = 16; off; off >>= 1)
                    part[c] += __shfl_xor_sync(0xffffffffu, part[c], off);
            }
            if (lane == 0) {
                #pragma unroll
                for (int c = 0; c < 7; c++) redf[par][warp * 7 + c] = part[c];
            }
            __syncthreads();               // barrier 1: partials ready
            if (tid < 7) {
                float t = redf[par][tid];
                #pragma unroll
                for (int w = 1; w < 16; w++) t += redf[par][w * 7 + tid];
                sh_tot[par][tid] = t;
            }
            __syncthreads();               // barrier 2: totals ready
            float nlo = lo, nhi = hi, nslo = slo, nshi = shi;
            bool crossed = false;
            #pragma unroll
            for (int c = 0; c < 7; c++) {
                float tc = lo + (c + 1) * step;
                float Sc = sh_tot[par][c];
                if (!crossed) {
                    if (Sc > BUDGETF) { nlo = tc; nslo = Sc; }
                    else { nhi = tc; nshi = Sc; crossed = true; }
                }
            }
            lo = nlo; hi = nhi; slo = nslo; shi = nshi;
        }
        float denom = slo - shi;
        tau = (denom > 1e-12f)
            ? lo + (slo - BUDGETF) * (hi - lo) / denom
            : 0.5f * (lo + hi);
    }

    int qe = qe_arr[b];
    int clen = len - 1;
    for (int p = tid; p < LC; p += NT) {
        float r;
        if (p < qe) {
            r = 1.f;
        } else {
            int idx = p - qe + 1;                 // >= 1
            r = (idx <= clen) ? clip01(sp[idx] - tau) : 0.f;
        }
        out[b * LC + p] = r;
    }
}

// ---------------------------------------------------------------------------
extern "C" void kernel_launch(void* const* d_in, const int* in_sizes, int n_in,
                              void* d_out, int out_size) {
    const float* question = (const float*)d_in[0];  // [B,1,H]
    const float* context  = (const float*)d_in[1];  // [B,LC,H]
    const float* Wq       = (const float*)d_in[2];  // [H,P]
    const float* bq       = (const float*)d_in[3];  // [P]
    const float* Wc       = (const float*)d_in[4];  // [H,P]
    const float* bc       = (const float*)d_in[5];  // [P]
    const int*   maskp    = (const int*)d_in[6];    // [B,LC]
    const int*   qep      = (const int*)d_in[7];    // [B]
    float* out = (float*)d_out;                     // [B,MAXLEN]

    qproj_kernel<<<NB, 512>>>(question, Wq, bq, bc, maskp);
    dim3 gu(NB, 4);
    uproj_kernel<<<gu, 256>>>(Wc);
    score_kernel<<<SCORE_BLOCKS, 256>>>(context);
    tau_kernel<<<NB, 512>>>(qep, out);
}

// round 14
// speedup vs baseline: 1.0719x; 1.0719x over previous
#include <cuda_runtime.h>

#define NB 64
#define LC 4096
#define HD 768
#define PD 128
#define BUDGETF 200.0f

// Scratch (allocation-free rule: __device__ globals)
__device__ float d_q[NB * PD];      // q_b = qr_b @ Wq + bq
__device__ float d_U[NB * HD];      // u_b = Wc @ q_b
__device__ float d_qbias[NB];       // q_b . bc
__device__ int   d_len[NB];         // valid context length per batch
__device__ float d_s[NB * LC];      // match scores (only [0,len) valid)

// ---------------------------------------------------------------------------
// Kernel 1a: q[b,p] = qr[b,:] . Wq[:,p] + bq[p] ; qbias[b] = q_b . bc ;
//            len[b] = sum(mask[b,:])      (measured-fast round-4 form)
// ---------------------------------------------------------------------------
__global__ void __launch_bounds__(512) qproj_kernel(const float* __restrict__ qr,
                                                    const float* __restrict__ Wq,
                                                    const float* __restrict__ bq,
                                                    const float* __restrict__ bc,
                                                    const int* __restrict__ mask) {
    int b = blockIdx.x;
    __shared__ float sh_qr[HD];
    __shared__ float sh_part[512];
    __shared__ int sh_cnt[16];
    int tid = threadIdx.x;

    for (int i = tid; i < HD; i += 512) sh_qr[i] = qr[b * HD + i];

    int cnt = 0;
    for (int i = tid; i < LC; i += 512) cnt += mask[b * LC + i];
    #pragma unroll
    for (int off = 16; off; off >>= 1) cnt += __shfl_xor_sync(0xffffffffu, cnt, off);
    if ((tid & 31) == 0) sh_cnt[tid >> 5] = cnt;
    __syncthreads();
    if (tid == 0) {
        int t = 0;
        #pragma unroll
        for (int w = 0; w < 16; w++) t += sh_cnt[w];
        d_len[b] = t;
    }

    int p = tid & 127;
    int slice = tid >> 7;            // 0..3
    int h0 = slice * (HD / 4);       // 192 rows per slice
    float a0 = 0.f, a1 = 0.f, a2 = 0.f, a3 = 0.f;
    #pragma unroll 4
    for (int h = h0; h < h0 + HD / 4; h += 4) {
        a0 = fmaf(sh_qr[h + 0], Wq[(h + 0) * PD + p], a0);
        a1 = fmaf(sh_qr[h + 1], Wq[(h + 1) * PD + p], a1);
        a2 = fmaf(sh_qr[h + 2], Wq[(h + 2) * PD + p], a2);
        a3 = fmaf(sh_qr[h + 3], Wq[(h + 3) * PD + p], a3);
    }
    sh_part[tid] = (a0 + a1) + (a2 + a3);
    __syncthreads();

    if (tid < PD) {
        float q = sh_part[tid] + sh_part[PD + tid] + sh_part[2 * PD + tid]
                + sh_part[3 * PD + tid] + bq[tid];
        d_q[b * PD + tid] = q;
        sh_part[tid] = q;
    }
    __syncthreads();

    if (tid < 32) {
        float v = 0.f;
        #pragma unroll
        for (int k = 0; k < 4; k++)
            v = fmaf(sh_part[tid + 32 * k], bc[tid + 32 * k], v);
        #pragma unroll
        for (int off = 16; off; off >>= 1)
            v += __shfl_xor_sync(0xffffffffu, v, off);
        if (tid == 0) d_qbias[b] = v;
    }
}

// ---------------------------------------------------------------------------
// Kernel 1b: u[b,h] = Wc[h,:] . q_b  (warp per h, lanes over p; grid 64x4)
// ---------------------------------------------------------------------------
__global__ void __launch_bounds__(256) uproj_kernel(const float* __restrict__ Wc) {
    int b = blockIdx.x;
    int chunk = blockIdx.y;
    __shared__ float sh_q[PD];
    int tid = threadIdx.x;
    if (tid < PD) sh_q[tid] = d_q[b * PD + tid];
    __syncthreads();

    int warp = tid >> 5, lane = tid & 31;
    for (int hh = warp; hh < HD / 4; hh += 8) {
        int h = chunk * (HD / 4) + hh;
        const float* wr = Wc + (size_t)h * PD;
        float acc = wr[lane] * sh_q[lane];
        acc = fmaf(wr[lane + 32], sh_q[lane + 32], acc);
        acc = fmaf(wr[lane + 64], sh_q[lane + 64], acc);
        acc = fmaf(wr[lane + 96], sh_q[lane + 96], acc);
        #pragma unroll
        for (int off = 16; off; off >>= 1)
            acc += __shfl_xor_sync(0xffffffffu, acc, off);
        if (lane == 0) d_U[b * HD + h] = acc;
    }
}

// ---------------------------------------------------------------------------
// Kernel 2: s[b,j] = ctx[b,j,:].u_b + qbias for j < len[b].
// Row-interleaved single-row loop (R11/R12 form — measured pattern ceiling,
// ~6.1 TB/s; 2-row pairing, work-stealing, and register hoisting all
// regressed against this form).
// ---------------------------------------------------------------------------
#define SCORE_BLOCKS 1184
#define NWARPS (SCORE_BLOCKS * 8)

__global__ void __launch_bounds__(256) score_kernel(const float* __restrict__ ctx) {
    __shared__ int sh_len[NB];
    __shared__ float sh_qb[NB];
    int tid = threadIdx.x;
    if (tid < NB) { sh_len[tid] = d_len[tid]; sh_qb[tid] = d_qbias[tid]; }
    __syncthreads();

    int warp = tid >> 5, lane = tid & 31;
    int gw = blockIdx.x * 8 + warp;

    for (int r = gw; r < NB * LC; r += NWARPS) {
        int b = r >> 12;                 // LC = 4096
        int j = r & (LC - 1);
        if (j >= sh_len[b]) continue;    // uniform within warp

        const float4* row = (const float4*)(ctx + (size_t)r * HD);
        const float4* u4  = (const float4*)(d_U + b * HD);
        float acc = 0.f;
        #pragma unroll
        for (int i = 0; i < 6; i++) {    // 192 float4 / 32 lanes
            float4 v = __ldcs(row + lane + 32 * i);
            float4 w = __ldg(u4 + lane + 32 * i);
            acc = fmaf(v.x, w.x, acc);
            acc = fmaf(v.y, w.y, acc);
            acc = fmaf(v.z, w.z, acc);
            acc = fmaf(v.w, w.w, acc);
        }
        #pragma unroll
        for (int off = 16; off; off >>= 1)
            acc += __shfl_xor_sync(0xffffffffu, acc, off);
        if (lane == 0) d_s[r] = acc + sh_qb[b];
    }
}

// ---------------------------------------------------------------------------
// Kernel 3: tau solve — 6 rounds of 8-ary search with tracked endpoint sums,
// final secant step (S piecewise-linear; bracket 1.9e-4 holds <=1 breakpoint
// so the secant is near-exact). Double-buffered partials -> 2 barriers/round.
// Fused scatter tail. (R12 form, measured 11.1us.)
// ---------------------------------------------------------------------------
__device__ __forceinline__ float clip01(float v) {
    return fminf(fmaxf(v, 0.f), 1.f);
}

__global__ void __launch_bounds__(512) tau_kernel(const int* __restrict__ qe_arr,
                                                  float* __restrict__ out) {
    int b = blockIdx.x;
    const int NT = 512;
    __shared__ float redf[2][16 * 7];
    __shared__ float sh_tot[2][8];
    int tid = threadIdx.x, warp = tid >> 5, lane = tid & 31;
    int len = d_len[b];
    const float* sp = d_s + b * LC;

    // register-resident values; invalid -> -1e5 (contributes 0, never max)
    float v[8];
    #pragma unroll
    for (int k = 0; k < 8; k++) {
        int i = tid + k * NT;
        v[k] = (i < len) ? sp[i] : -100000.0f;
    }

    // max and z_sum(0), fused hierarchical block reduce
    float mx = -100000.0f, sum0 = 0.f;
    #pragma unroll
    for (int k = 0; k < 8; k++) {
        mx = fmaxf(mx, v[k]);
        sum0 += clip01(v[k]);
    }
    {
        #pragma unroll
        for (int off = 16; off; off >>= 1) {
            mx   = fmaxf(mx, __shfl_xor_sync(0xffffffffu, mx, off));
            sum0 += __shfl_xor_sync(0xffffffffu, sum0, off);
        }
        if (lane == 0) { redf[0][warp * 2] = mx; redf[0][warp * 2 + 1] = sum0; }
        __syncthreads();
        if (tid == 0) {
            float a = redf[0][0], s = redf[0][1];
            #pragma unroll
            for (int w = 1; w < 16; w++) {
                a = fmaxf(a, redf[0][w * 2]);
                s += redf[0][w * 2 + 1];
            }
            sh_tot[1][0] = a; sh_tot[1][1] = s;   // park in buffer 1 (round 0 uses buffer 0)
        }
        __syncthreads();
        mx = sh_tot[1][0]; sum0 = sh_tot[1][1];
    }

    float tau = 0.f;
    if (sum0 > BUDGETF) {
        float lo = 0.f, hi = mx;
        float slo = sum0, shi = 0.f;      // S at the bracket endpoints
        for (int it = 0; it < 6; it++) {
            int par = it & 1;
            float step = (hi - lo) * 0.125f;
            float part[7];
            #pragma unroll
            for (int c = 0; c < 7; c++) part[c] = 0.f;
            #pragma unroll
            for (int k = 0; k < 8; k++) {
                float x = v[k] - lo;
                #pragma unroll
                for (int c = 0; c < 7; c++)
                    part[c] += clip01(x - (c + 1) * step);
            }
            #pragma unroll
            for (int c = 0; c < 7; c++) {
                #pragma unroll
                for (int off = 16; off; off >>= 1)
                    part[c] += __shfl_xor_sync(0xffffffffu, part[c], off);
            }
            if (lane == 0) {
                #pragma unroll
                for (int c = 0; c < 7; c++) redf[par][warp * 7 + c] = part[c];
            }
            __syncthreads();               // barrier 1: partials ready
            if (tid < 7) {
                float t = redf[par][tid];
                #pragma unroll
                for (int w = 1; w < 16; w++) t += redf[par][w * 7 + tid];
                sh_tot[par][tid] = t;
            }
            __syncthreads();               // barrier 2: totals ready
            // S non-increasing: lo -> last candidate with S>BUDGET,
            // hi -> first with S<=BUDGET. Track endpoint sums for secant.
            float nlo = lo, nhi = hi, nslo = slo, nshi = shi;
            bool crossed = false;
            #pragma unroll
            for (int c = 0; c < 7; c++) {
                float tc = lo + (c + 1) * step;
                float Sc = sh_tot[par][c];
                if (!crossed) {
                    if (Sc > BUDGETF) { nlo = tc; nslo = Sc; }
                    else { nhi = tc; nshi = Sc; crossed = true; }
                }
            }
            lo = nlo; hi = nhi; slo = nslo; shi = nshi;
            // no 3rd barrier: next round writes the OTHER parity buffer; its
            // barrier 1 orders these reads before this buffer is rewritten.
        }
        // final secant step on the (near-)linear segment
        float denom = slo - shi;
        tau = (denom > 1e-12f)
            ? lo + (slo - BUDGETF) * (hi - lo) / denom
            : 0.5f * (lo + hi);
    }

    // fused scatter tail: out[b,p] = 1 | clip01(s[idx]-tau) | 0
    int qe = qe_arr[b];
    int clen = len - 1;
    for (int p = tid; p < LC; p += NT) {
        float r;
        if (p < qe) {
            r = 1.f;
        } else {
            int idx = p - qe + 1;                 // >= 1
            r = (idx <= clen) ? clip01(sp[idx] - tau) : 0.f;
        }
        out[b * LC + p] = r;
    }
}

// ---------------------------------------------------------------------------
extern "C" void kernel_launch(void* const* d_in, const int* in_sizes, int n_in,
                              void* d_out, int out_size) {
    const float* question = (const float*)d_in[0];  // [B,1,H]
    const float* context  = (const float*)d_in[1];  // [B,LC,H]
    const float* Wq       = (const float*)d_in[2];  // [H,P]
    const float* bq       = (const float*)d_in[3];  // [P]
    const float* Wc       = (const float*)d_in[4];  // [H,P]
    const float* bc       = (const float*)d_in[5];  // [P]
    const int*   maskp    = (const int*)d_in[6];    // [B,LC]
    const int*   qep      = (const int*)d_in[7];    // [B]
    float* out = (float*)d_out;                     // [B,MAXLEN]

    qproj_kernel<<<NB, 512>>>(question, Wq, bq, bc, maskp);
    dim3 gu(NB, 4);
    uproj_kernel<<<gu, 256>>>(Wc);
    score_kernel<<<SCORE_BLOCKS, 256>>>(context);
    tau_kernel<<<NB, 512>>>(qep, out);
}

// round 15
// speedup vs baseline: 1.0831x; 1.0105x over previous
#include <cuda_runtime.h>

#define NB 64
#define LC 4096
#define HD 768
#define PD 128
#define BUDGETF 200.0f

// Scratch (allocation-free rule: __device__ globals)
__device__ float d_U[NB * HD];      // u_b = Wc @ q_b
__device__ float d_qbias[NB];       // q_b . bc
__device__ int   d_len[NB];         // valid context length per batch
__device__ float d_s[NB * LC];      // match scores (only [0,len) valid)

// ---------------------------------------------------------------------------
// Kernel 1 (fused, grid 64x4): every block recomputes q_b (redundant stage A,
// Wq is L2-resident so the 4x re-read is free), then computes its 192-row
// chunk of u_b = Wc @ q_b with 16 warps (coalesced, 256-block parallelism —
// the property R5's 64-block fusion lacked). Chunk-0 blocks also do the mask
// count and qbias.
// ---------------------------------------------------------------------------
__global__ void __launch_bounds__(512) proj_kernel(const float* __restrict__ qr,
                                                   const float* __restrict__ Wq,
                                                   const float* __restrict__ bq,
                                                   const float* __restrict__ Wc,
                                                   const float* __restrict__ bc,
                                                   const int* __restrict__ mask) {
    int b = blockIdx.x;
    int chunk = blockIdx.y;           // 0..3, owns h in [chunk*192, chunk*192+192)
    __shared__ float sh_qr[HD];
    __shared__ float sh_part[512];
    __shared__ float sh_q[PD];
    __shared__ int sh_cnt[16];
    int tid = threadIdx.x;
    int warp = tid >> 5, lane = tid & 31;

    for (int i = tid; i < HD; i += 512) sh_qr[i] = qr[b * HD + i];

    // len[b] = sum(mask[b,:])   (chunk 0 only)
    if (chunk == 0) {
        int cnt = 0;
        for (int i = tid; i < LC; i += 512) cnt += mask[b * LC + i];
        #pragma unroll
        for (int off = 16; off; off >>= 1)
            cnt += __shfl_xor_sync(0xffffffffu, cnt, off);
        if (lane == 0) sh_cnt[warp] = cnt;
    }
    __syncthreads();
    if (chunk == 0 && tid == 0) {
        int t = 0;
        #pragma unroll
        for (int w = 0; w < 16; w++) t += sh_cnt[w];
        d_len[b] = t;
    }

    // Stage A (redundant per block): q[p] = qr . Wq[:,p] + bq[p]
    int p = tid & 127;
    int slice = tid >> 7;             // 0..3
    int h0 = slice * (HD / 4);        // 192 rows per slice
    float a0 = 0.f, a1 = 0.f, a2 = 0.f, a3 = 0.f;
    #pragma unroll 4
    for (int h = h0; h < h0 + HD / 4; h += 4) {
        a0 = fmaf(sh_qr[h + 0], Wq[(h + 0) * PD + p], a0);
        a1 = fmaf(sh_qr[h + 1], Wq[(h + 1) * PD + p], a1);
        a2 = fmaf(sh_qr[h + 2], Wq[(h + 2) * PD + p], a2);
        a3 = fmaf(sh_qr[h + 3], Wq[(h + 3) * PD + p], a3);
    }
    sh_part[tid] = (a0 + a1) + (a2 + a3);
    __syncthreads();

    if (tid < PD) {
        sh_q[tid] = sh_part[tid] + sh_part[PD + tid] + sh_part[2 * PD + tid]
                  + sh_part[3 * PD + tid] + bq[tid];
    }
    __syncthreads();

    // qbias = q . bc   (chunk 0 only)
    if (chunk == 0 && tid < 32) {
        float v = 0.f;
        #pragma unroll
        for (int k = 0; k < 4; k++)
            v = fmaf(sh_q[tid + 32 * k], bc[tid + 32 * k], v);
        #pragma unroll
        for (int off = 16; off; off >>= 1)
            v += __shfl_xor_sync(0xffffffffu, v, off);
        if (tid == 0) d_qbias[b] = v;
    }

    // Stage B: u[h] = Wc[h,:] . q for this chunk's 192 rows (16 warps)
    for (int hh = warp; hh < HD / 4; hh += 16) {
        int h = chunk * (HD / 4) + hh;
        const float* wr = Wc + (size_t)h * PD;
        float acc = wr[lane] * sh_q[lane];
        acc = fmaf(wr[lane + 32], sh_q[lane + 32], acc);
        acc = fmaf(wr[lane + 64], sh_q[lane + 64], acc);
        acc = fmaf(wr[lane + 96], sh_q[lane + 96], acc);
        #pragma unroll
        for (int off = 16; off; off >>= 1)
            acc += __shfl_xor_sync(0xffffffffu, acc, off);
        if (lane == 0) d_U[b * HD + h] = acc;
    }
}

// ---------------------------------------------------------------------------
// Kernel 2: s[b,j] = ctx[b,j,:].u_b + qbias for j < len[b].
// Row-interleaved single-row loop (measured pattern ceiling ~6.1 TB/s).
// ---------------------------------------------------------------------------
#define SCORE_BLOCKS 1184
#define NWARPS (SCORE_BLOCKS * 8)

__global__ void __launch_bounds__(256) score_kernel(const float* __restrict__ ctx) {
    __shared__ int sh_len[NB];
    __shared__ float sh_qb[NB];
    int tid = threadIdx.x;
    if (tid < NB) { sh_len[tid] = d_len[tid]; sh_qb[tid] = d_qbias[tid]; }
    __syncthreads();

    int warp = tid >> 5, lane = tid & 31;
    int gw = blockIdx.x * 8 + warp;

    for (int r = gw; r < NB * LC; r += NWARPS) {
        int b = r >> 12;                 // LC = 4096
        int j = r & (LC - 1);
        if (j >= sh_len[b]) continue;    // uniform within warp

        const float4* row = (const float4*)(ctx + (size_t)r * HD);
        const float4* u4  = (const float4*)(d_U + b * HD);
        float acc = 0.f;
        #pragma unroll
        for (int i = 0; i < 6; i++) {    // 192 float4 / 32 lanes
            float4 v = __ldcs(row + lane + 32 * i);
            float4 w = __ldg(u4 + lane + 32 * i);
            acc = fmaf(v.x, w.x, acc);
            acc = fmaf(v.y, w.y, acc);
            acc = fmaf(v.z, w.z, acc);
            acc = fmaf(v.w, w.w, acc);
        }
        #pragma unroll
        for (int off = 16; off; off >>= 1)
            acc += __shfl_xor_sync(0xffffffffu, acc, off);
        if (lane == 0) d_s[r] = acc + sh_qb[b];
    }
}

// ---------------------------------------------------------------------------
// Kernel 3: tau solve — 6 rounds of 8-ary search with tracked endpoint sums,
// final secant step. 2 barriers/round via double-buffered partials.
// Fused scatter tail. (R12 form, measured 10.8us.)
// ---------------------------------------------------------------------------
__device__ __forceinline__ float clip01(float v) {
    return fminf(fmaxf(v, 0.f), 1.f);
}

__global__ void __launch_bounds__(512) tau_kernel(const int* __restrict__ qe_arr,
                                                  float* __restrict__ out) {
    int b = blockIdx.x;
    const int NT = 512;
    __shared__ float redf[2][16 * 7];
    __shared__ float sh_tot[2][8];
    int tid = threadIdx.x, warp = tid >> 5, lane = tid & 31;
    int len = d_len[b];
    const float* sp = d_s + b * LC;

    // register-resident values; invalid -> -1e5 (contributes 0, never max)
    float v[8];
    #pragma unroll
    for (int k = 0; k < 8; k++) {
        int i = tid + k * NT;
        v[k] = (i < len) ? sp[i] : -100000.0f;
    }

    // max and z_sum(0), fused hierarchical block reduce
    float mx = -100000.0f, sum0 = 0.f;
    #pragma unroll
    for (int k = 0; k < 8; k++) {
        mx = fmaxf(mx, v[k]);
        sum0 += clip01(v[k]);
    }
    {
        #pragma unroll
        for (int off = 16; off; off >>= 1) {
            mx   = fmaxf(mx, __shfl_xor_sync(0xffffffffu, mx, off));
            sum0 += __shfl_xor_sync(0xffffffffu, sum0, off);
        }
        if (lane == 0) { redf[0][warp * 2] = mx; redf[0][warp * 2 + 1] = sum0; }
        __syncthreads();
        if (tid == 0) {
            float a = redf[0][0], s = redf[0][1];
            #pragma unroll
            for (int w = 1; w < 16; w++) {
                a = fmaxf(a, redf[0][w * 2]);
                s += redf[0][w * 2 + 1];
            }
            sh_tot[1][0] = a; sh_tot[1][1] = s;   // park in buffer 1 (round 0 uses buffer 0)
        }
        __syncthreads();
        mx = sh_tot[1][0]; sum0 = sh_tot[1][1];
    }

    float tau = 0.f;
    if (sum0 > BUDGETF) {
        float lo = 0.f, hi = mx;
        float slo = sum0, shi = 0.f;      // S at the bracket endpoints
        for (int it = 0; it < 6; it++) {
            int par = it & 1;
            float step = (hi - lo) * 0.125f;
            float part[7];
            #pragma unroll
            for (int c = 0; c < 7; c++) part[c] = 0.f;
            #pragma unroll
            for (int k = 0; k < 8; k++) {
                float x = v[k] - lo;
                #pragma unroll
                for (int c = 0; c < 7; c++)
                    part[c] += clip01(x - (c + 1) * step);
            }
            #pragma unroll
            for (int c = 0; c < 7; c++) {
                #pragma unroll
                for (int off = 16; off; off >>= 1)
                    part[c] += __shfl_xor_sync(0xffffffffu, part[c], off);
            }
            if (lane == 0) {
                #pragma unroll
                for (int c = 0; c < 7; c++) redf[par][warp * 7 + c] = part[c];
            }
            __syncthreads();               // barrier 1: partials ready
            if (tid < 7) {
                float t = redf[par][tid];
                #pragma unroll
                for (int w = 1; w < 16; w++) t += redf[par][w * 7 + tid];
                sh_tot[par][tid] = t;
            }
            __syncthreads();               // barrier 2: totals ready
            // S non-increasing: lo -> last candidate with S>BUDGET,
            // hi -> first with S<=BUDGET. Track endpoint sums for secant.
            float nlo = lo, nhi = hi, nslo = slo, nshi = shi;
            bool crossed = false;
            #pragma unroll
            for (int c = 0; c < 7; c++) {
                float tc = lo + (c + 1) * step;
                float Sc = sh_tot[par][c];
                if (!crossed) {
                    if (Sc > BUDGETF) { nlo = tc; nslo = Sc; }
                    else { nhi = tc; nshi = Sc; crossed = true; }
                }
            }
            lo = nlo; hi = nhi; slo = nslo; shi = nshi;
            // no 3rd barrier: next round writes the OTHER parity buffer; its
            // barrier 1 orders these reads before this buffer is rewritten.
        }
        // final secant step on the (near-)linear segment
        float denom = slo - shi;
        tau = (denom > 1e-12f)
            ? lo + (slo - BUDGETF) * (hi - lo) / denom
            : 0.5f * (lo + hi);
    }

    // fused scatter tail: out[b,p] = 1 | clip01(s[idx]-tau) | 0
    int qe = qe_arr[b];
    int clen = len - 1;
    for (int p = tid; p < LC; p += NT) {
        float r;
        if (p < qe) {
            r = 1.f;
        } else {
            int idx = p - qe + 1;                 // >= 1
            r = (idx <= clen) ? clip01(sp[idx] - tau) : 0.f;
        }
        out[b * LC + p] = r;
    }
}

// ---------------------------------------------------------------------------
extern "C" void kernel_launch(void* const* d_in, const int* in_sizes, int n_in,
                              void* d_out, int out_size) {
    const float* question = (const float*)d_in[0];  // [B,1,H]
    const float* context  = (const float*)d_in[1];  // [B,LC,H]
    const float* Wq       = (const float*)d_in[2];  // [H,P]
    const float* bq       = (const float*)d_in[3];  // [P]
    const float* Wc       = (const float*)d_in[4];  // [H,P]
    const float* bc       = (const float*)d_in[5];  // [P]
    const int*   maskp    = (const int*)d_in[6];    // [B,LC]
    const int*   qep      = (const int*)d_in[7];    // [B]
    float* out = (float*)d_out;                     // [B,MAXLEN]

    dim3 gp(NB, 4);
    proj_kernel<<<gp, 512>>>(question, Wq, bq, Wc, bc, maskp);
    score_kernel<<<SCORE_BLOCKS, 256>>>(context);
    tau_kernel<<<NB, 512>>>(qep, out);
}